// round 13
// baseline (speedup 1.0000x reference)
#include <cuda_runtime.h>
#include <cuda_bf16.h>

#define NCAM 16

// ---------- f32x2 packed-math helpers (sm_103a) ----------
__device__ __forceinline__ unsigned long long pk2(float a, float b) {
    unsigned long long r;
    asm("mov.b64 %0, {%1, %2};" : "=l"(r) : "f"(a), "f"(b));
    return r;
}
__device__ __forceinline__ void upk2(unsigned long long v, float& a, float& b) {
    asm("mov.b64 {%0, %1}, %2;" : "=f"(a), "=f"(b) : "l"(v));
}
__device__ __forceinline__ unsigned long long fma2(unsigned long long a,
                                                   unsigned long long b,
                                                   unsigned long long c) {
    unsigned long long d;
    asm("fma.rn.f32x2 %0, %1, %2, %3;" : "=l"(d) : "l"(a), "l"(b), "l"(c));
    return d;
}
__device__ __forceinline__ unsigned long long mul2(unsigned long long a,
                                                   unsigned long long b) {
    unsigned long long d;
    asm("mul.rn.f32x2 %0, %1, %2;" : "=l"(d) : "l"(a), "l"(b));
    return d;
}
__device__ __forceinline__ float frcp(float x) {
    float r;
    asm("rcp.approx.f32 %0, %1;" : "=f"(r) : "f"(x));
    return r;
}

// Shared param layout per camera: 16 duplicated (v,v) pairs (128 B):
//   k 0..8 : r00 r01 r02 r10 r11 r12 r20 r21 r22
//   k 9..11: t0 t1 t2    k 12,13: f0 f1    k 14,15: c0 c1
// each stored as (v, v) so it is directly an f32x2 broadcast operand.

__global__ __launch_bounds__(256, 5)
void Projection_19713899889207_kernel(
    const float* __restrict__ pt3d,   // (3, Np) SoA
    const float* __restrict__ R,      // (NC, 3, 3)
    const float* __restrict__ t,      // (NC, 3)
    const float* __restrict__ f,      // (NC, 2)
    const float* __restrict__ c,      // (NC, 2)
    float* __restrict__ out,          // (NC*Np, 2)
    int np)
{
    __shared__ __align__(16) float sp[NCAM * 32];

    const int tid = threadIdx.x;
    // stage 512 floats with 256 threads (2 each) — no extra launches needed
    #pragma unroll
    for (int s = tid; s < NCAM * 32; s += 256) {
        const int cam = s >> 5;
        const int k   = (s & 31) >> 1;
        float v;
        if (k < 9)       v = R[cam * 9 + k];
        else if (k < 12) v = t[cam * 3 + (k - 9)];
        else if (k < 14) v = f[cam * 2 + (k - 12)];
        else             v = c[cam * 2 + (k - 14)];
        sp[s] = v;
    }
    __syncthreads();

    const int i = blockIdx.x * blockDim.x + tid;   // index of a PAIR of points
    const int np2 = np >> 1;
    if (i >= np2) return;

    // Two adjacent floats loaded as u64 == the f32x2 operand (x_j, x_{j+1}).
    const unsigned long long x01 =
        __ldg(reinterpret_cast<const unsigned long long*>(pt3d) + i);
    const unsigned long long y01 =
        __ldg(reinterpret_cast<const unsigned long long*>(pt3d + (size_t)np) + i);
    const unsigned long long z01 =
        __ldg(reinterpret_cast<const unsigned long long*>(pt3d + 2 * (size_t)np) + i);

    // Incremental output pointer: one float4 (2 points) per camera.
    float4* o = reinterpret_cast<float4*>(out) + (size_t)i;
    const size_t cam_stride_f4 = (size_t)(np >> 1);

    #pragma unroll 1
    for (int cam = 0; cam < NCAM; ++cam) {
        const ulonglong2* Q = reinterpret_cast<const ulonglong2*>(sp + cam * 32);
        const ulonglong2 q0 = Q[0];  // (r00d, r01d)
        const ulonglong2 q1 = Q[1];  // (r02d, r10d)
        const ulonglong2 q2 = Q[2];  // (r11d, r12d)
        const ulonglong2 q3 = Q[3];  // (r20d, r21d)
        const ulonglong2 q4 = Q[4];  // (r22d, t0d)
        const ulonglong2 q5 = Q[5];  // (t1d,  t2d)
        const ulonglong2 q6 = Q[6];  // (f0d,  f1d)
        const ulonglong2 q7 = Q[7];  // (c0d,  c1d)

        const unsigned long long X =
            fma2(q0.x, x01, fma2(q0.y, y01, fma2(q1.x, z01, q4.y)));
        const unsigned long long Y =
            fma2(q1.y, x01, fma2(q2.x, y01, fma2(q2.y, z01, q5.x)));
        const unsigned long long Z =
            fma2(q3.x, x01, fma2(q3.y, y01, fma2(q4.x, z01, q5.y)));

        float z0, z1;
        upk2(Z, z0, z1);
        const unsigned long long IZ = pk2(frcp(z0), frcp(z1));

        const unsigned long long U = fma2(mul2(X, IZ), q6.x, q7.x);
        const unsigned long long V = fma2(mul2(Y, IZ), q6.y, q7.y);

        float u0, u1, v0, v1;
        upk2(U, u0, u1);
        upk2(V, v0, v1);

        // A/B vs champion: DEFAULT cache policy (was __stcs / evict-first).
        // Let the 126MB L2 buffer and smooth the 256MB write stream.
        *o = make_float4(u0, v0, u1, v1);
        o += cam_stride_f4;
    }
}

extern "C" void kernel_launch(void* const* d_in, const int* in_sizes, int n_in,
                              void* d_out, int out_size)
{
    // metadata order: pt3d (3,Np) f32, R (16,3,3) f32, t (16,3) f32,
    //                 f (16,2) f32, c (16,2) f32, mask (16,Np) i32 (unused)
    const float* pt3d = (const float*)d_in[0];
    const float* R    = (const float*)d_in[1];
    const float* t    = (const float*)d_in[2];
    const float* f    = (const float*)d_in[3];
    const float* c    = (const float*)d_in[4];
    float* out        = (float*)d_out;

    const int np  = in_sizes[0] / 3;        // 2,000,000
    const int np2 = np / 2;
    const int threads = 256;
    const int blocks  = (np2 + threads - 1) / threads;

    Projection_19713899889207_kernel<<<blocks, threads>>>(pt3d, R, t, f, c, out, np);
}

// round 14
// speedup vs baseline: 1.1419x; 1.1419x over previous
#include <cuda_runtime.h>
#include <cuda_bf16.h>

#define NCAM 16

// ---------- f32x2 packed-math helpers (sm_103a) ----------
__device__ __forceinline__ unsigned long long pk2(float a, float b) {
    unsigned long long r;
    asm("mov.b64 %0, {%1, %2};" : "=l"(r) : "f"(a), "f"(b));
    return r;
}
__device__ __forceinline__ void upk2(unsigned long long v, float& a, float& b) {
    asm("mov.b64 {%0, %1}, %2;" : "=f"(a), "=f"(b) : "l"(v));
}
__device__ __forceinline__ unsigned long long fma2(unsigned long long a,
                                                   unsigned long long b,
                                                   unsigned long long c) {
    unsigned long long d;
    asm("fma.rn.f32x2 %0, %1, %2, %3;" : "=l"(d) : "l"(a), "l"(b), "l"(c));
    return d;
}
__device__ __forceinline__ unsigned long long mul2(unsigned long long a,
                                                   unsigned long long b) {
    unsigned long long d;
    asm("mul.rn.f32x2 %0, %1, %2;" : "=l"(d) : "l"(a), "l"(b));
    return d;
}
__device__ __forceinline__ float frcp(float x) {
    float r;
    asm("rcp.approx.f32 %0, %1;" : "=f"(r) : "f"(x));
    return r;
}

// Shared param layout per camera: 16 duplicated (v,v) pairs (128 B):
//   k 0..8 : r00 r01 r02 r10 r11 r12 r20 r21 r22
//   k 9..11: t0 t1 t2    k 12,13: f0 f1    k 14,15: c0 c1
// each stored as (v, v) so it is directly an f32x2 broadcast operand.

__global__ __launch_bounds__(256, 5)
void Projection_19713899889207_kernel(
    const float* __restrict__ pt3d,   // (3, Np) SoA
    const float* __restrict__ R,      // (NC, 3, 3)
    const float* __restrict__ t,      // (NC, 3)
    const float* __restrict__ f,      // (NC, 2)
    const float* __restrict__ c,      // (NC, 2)
    float* __restrict__ out,          // (NC*Np, 2)
    int np)
{
    __shared__ __align__(16) float sp[NCAM * 32];

    const int tid = threadIdx.x;
    // stage 512 floats with 256 threads (2 each)
    #pragma unroll
    for (int s = tid; s < NCAM * 32; s += 256) {
        const int cam = s >> 5;
        const int k   = (s & 31) >> 1;
        float v;
        if (k < 9)       v = R[cam * 9 + k];
        else if (k < 12) v = t[cam * 3 + (k - 9)];
        else if (k < 14) v = f[cam * 2 + (k - 12)];
        else             v = c[cam * 2 + (k - 14)];
        sp[s] = v;
    }
    __syncthreads();

    const int i = blockIdx.x * blockDim.x + tid;   // index of a PAIR of points
    const int np2 = np >> 1;
    if (i >= np2) return;

    // Two adjacent floats loaded as u64 == the f32x2 operand (x_j, x_{j+1}).
    const unsigned long long x01 =
        __ldg(reinterpret_cast<const unsigned long long*>(pt3d) + i);
    const unsigned long long y01 =
        __ldg(reinterpret_cast<const unsigned long long*>(pt3d + (size_t)np) + i);
    const unsigned long long z01 =
        __ldg(reinterpret_cast<const unsigned long long*>(pt3d + 2 * (size_t)np) + i);

    // Incremental output pointer: one float4 (2 points) per camera.
    float4* o = reinterpret_cast<float4*>(out) + (size_t)i;
    const size_t cam_stride_f4 = (size_t)(np >> 1);

    // unroll 2: interleave two independent per-camera dependency chains
    // (LDS -> FMA comb -> RCP -> store) to raise issue density; keeps reg
    // pressure below the 51-reg cap unlike full unroll.
    #pragma unroll 2
    for (int cam = 0; cam < NCAM; ++cam) {
        const ulonglong2* Q = reinterpret_cast<const ulonglong2*>(sp + cam * 32);
        const ulonglong2 q0 = Q[0];  // (r00d, r01d)
        const ulonglong2 q1 = Q[1];  // (r02d, r10d)
        const ulonglong2 q2 = Q[2];  // (r11d, r12d)
        const ulonglong2 q3 = Q[3];  // (r20d, r21d)
        const ulonglong2 q4 = Q[4];  // (r22d, t0d)
        const ulonglong2 q5 = Q[5];  // (t1d,  t2d)
        const ulonglong2 q6 = Q[6];  // (f0d,  f1d)
        const ulonglong2 q7 = Q[7];  // (c0d,  c1d)

        const unsigned long long X =
            fma2(q0.x, x01, fma2(q0.y, y01, fma2(q1.x, z01, q4.y)));
        const unsigned long long Y =
            fma2(q1.y, x01, fma2(q2.x, y01, fma2(q2.y, z01, q5.x)));
        const unsigned long long Z =
            fma2(q3.x, x01, fma2(q3.y, y01, fma2(q4.x, z01, q5.y)));

        float z0, z1;
        upk2(Z, z0, z1);
        const unsigned long long IZ = pk2(frcp(z0), frcp(z1));

        const unsigned long long U = fma2(mul2(X, IZ), q6.x, q7.x);
        const unsigned long long V = fma2(mul2(Y, IZ), q6.y, q7.y);

        float u0, u1, v0, v1;
        upk2(U, u0, u1);
        upk2(V, v0, v1);

        // streaming store: evict-first (.cs) is load-bearing — R12 showed
        // default policy poisons the next graph replay with dirty L2 flushes.
        __stcs(o, make_float4(u0, v0, u1, v1));
        o += cam_stride_f4;
    }
}

extern "C" void kernel_launch(void* const* d_in, const int* in_sizes, int n_in,
                              void* d_out, int out_size)
{
    // metadata order: pt3d (3,Np) f32, R (16,3,3) f32, t (16,3) f32,
    //                 f (16,2) f32, c (16,2) f32, mask (16,Np) i32 (unused)
    const float* pt3d = (const float*)d_in[0];
    const float* R    = (const float*)d_in[1];
    const float* t    = (const float*)d_in[2];
    const float* f    = (const float*)d_in[3];
    const float* c    = (const float*)d_in[4];
    float* out        = (float*)d_out;

    const int np  = in_sizes[0] / 3;        // 2,000,000
    const int np2 = np / 2;
    const int threads = 256;
    const int blocks  = (np2 + threads - 1) / threads;

    Projection_19713899889207_kernel<<<blocks, threads>>>(pt3d, R, t, f, c, out, np);
}

// round 15
// speedup vs baseline: 1.1428x; 1.0007x over previous
#include <cuda_runtime.h>
#include <cuda_bf16.h>

#define NCAM 16

// ---------- f32x2 packed-math helpers (sm_103a) ----------
__device__ __forceinline__ unsigned long long pk2(float a, float b) {
    unsigned long long r;
    asm("mov.b64 %0, {%1, %2};" : "=l"(r) : "f"(a), "f"(b));
    return r;
}
__device__ __forceinline__ void upk2(unsigned long long v, float& a, float& b) {
    asm("mov.b64 {%0, %1}, %2;" : "=f"(a), "=f"(b) : "l"(v));
}
__device__ __forceinline__ unsigned long long fma2(unsigned long long a,
                                                   unsigned long long b,
                                                   unsigned long long c) {
    unsigned long long d;
    asm("fma.rn.f32x2 %0, %1, %2, %3;" : "=l"(d) : "l"(a), "l"(b), "l"(c));
    return d;
}
__device__ __forceinline__ unsigned long long mul2(unsigned long long a,
                                                   unsigned long long b) {
    unsigned long long d;
    asm("mul.rn.f32x2 %0, %1, %2;" : "=l"(d) : "l"(a), "l"(b));
    return d;
}
__device__ __forceinline__ float frcp(float x) {
    float r;
    asm("rcp.approx.f32 %0, %1;" : "=f"(r) : "f"(x));
    return r;
}

// Shared param layout per camera: 16 duplicated (v,v) pairs (128 B):
//   k 0..8 : r00 r01 r02 r10 r11 r12 r20 r21 r22
//   k 9..11: t0 t1 t2    k 12,13: f0 f1    k 14,15: c0 c1
// each stored as (v, v) so it is directly an f32x2 broadcast operand.

// Champion R4 body; only change vs champion: 6 blocks/SM (regs measured
// exactly 42 = the (256,6) cap) -> 48 resident warps to cover DRAM-write
// backpressure stalls.
__global__ __launch_bounds__(256, 6)
void Projection_19713899889207_kernel(
    const float* __restrict__ pt3d,   // (3, Np) SoA
    const float* __restrict__ R,      // (NC, 3, 3)
    const float* __restrict__ t,      // (NC, 3)
    const float* __restrict__ f,      // (NC, 2)
    const float* __restrict__ c,      // (NC, 2)
    float* __restrict__ out,          // (NC*Np, 2)
    int np)
{
    __shared__ __align__(16) float sp[NCAM * 32];

    const int tid = threadIdx.x;
    // stage 512 floats with 256 threads (2 each)
    #pragma unroll
    for (int s = tid; s < NCAM * 32; s += 256) {
        const int cam = s >> 5;
        const int k   = (s & 31) >> 1;
        float v;
        if (k < 9)       v = R[cam * 9 + k];
        else if (k < 12) v = t[cam * 3 + (k - 9)];
        else if (k < 14) v = f[cam * 2 + (k - 12)];
        else             v = c[cam * 2 + (k - 14)];
        sp[s] = v;
    }
    __syncthreads();

    const int i = blockIdx.x * blockDim.x + tid;   // index of a PAIR of points
    const int np2 = np >> 1;
    if (i >= np2) return;

    // Two adjacent floats loaded as u64 == the f32x2 operand (x_j, x_{j+1}).
    const unsigned long long x01 =
        __ldg(reinterpret_cast<const unsigned long long*>(pt3d) + i);
    const unsigned long long y01 =
        __ldg(reinterpret_cast<const unsigned long long*>(pt3d + (size_t)np) + i);
    const unsigned long long z01 =
        __ldg(reinterpret_cast<const unsigned long long*>(pt3d + 2 * (size_t)np) + i);

    // Incremental output pointer: one float4 (2 points) per camera.
    float4* o = reinterpret_cast<float4*>(out) + (size_t)i;
    const size_t cam_stride_f4 = (size_t)(np >> 1);

    #pragma unroll 1
    for (int cam = 0; cam < NCAM; ++cam) {
        const ulonglong2* Q = reinterpret_cast<const ulonglong2*>(sp + cam * 32);
        const ulonglong2 q0 = Q[0];  // (r00d, r01d)
        const ulonglong2 q1 = Q[1];  // (r02d, r10d)
        const ulonglong2 q2 = Q[2];  // (r11d, r12d)
        const ulonglong2 q3 = Q[3];  // (r20d, r21d)
        const ulonglong2 q4 = Q[4];  // (r22d, t0d)
        const ulonglong2 q5 = Q[5];  // (t1d,  t2d)
        const ulonglong2 q6 = Q[6];  // (f0d,  f1d)
        const ulonglong2 q7 = Q[7];  // (c0d,  c1d)

        const unsigned long long X =
            fma2(q0.x, x01, fma2(q0.y, y01, fma2(q1.x, z01, q4.y)));
        const unsigned long long Y =
            fma2(q1.y, x01, fma2(q2.x, y01, fma2(q2.y, z01, q5.x)));
        const unsigned long long Z =
            fma2(q3.x, x01, fma2(q3.y, y01, fma2(q4.x, z01, q5.y)));

        float z0, z1;
        upk2(Z, z0, z1);
        const unsigned long long IZ = pk2(frcp(z0), frcp(z1));

        const unsigned long long U = fma2(mul2(X, IZ), q6.x, q7.x);
        const unsigned long long V = fma2(mul2(Y, IZ), q6.y, q7.y);

        float u0, u1, v0, v1;
        upk2(U, u0, u1);
        upk2(V, v0, v1);

        // streaming store (.cs evict-first is load-bearing — R12 regression)
        __stcs(o, make_float4(u0, v0, u1, v1));
        o += cam_stride_f4;
    }
}

extern "C" void kernel_launch(void* const* d_in, const int* in_sizes, int n_in,
                              void* d_out, int out_size)
{
    // metadata order: pt3d (3,Np) f32, R (16,3,3) f32, t (16,3) f32,
    //                 f (16,2) f32, c (16,2) f32, mask (16,Np) i32 (unused)
    const float* pt3d = (const float*)d_in[0];
    const float* R    = (const float*)d_in[1];
    const float* t    = (const float*)d_in[2];
    const float* f    = (const float*)d_in[3];
    const float* c    = (const float*)d_in[4];
    float* out        = (float*)d_out;

    const int np  = in_sizes[0] / 3;        // 2,000,000
    const int np2 = np / 2;
    const int threads = 256;
    const int blocks  = (np2 + threads - 1) / threads;

    Projection_19713899889207_kernel<<<blocks, threads>>>(pt3d, R, t, f, c, out, np);
}

// round 16
// speedup vs baseline: 1.1486x; 1.0052x over previous
#include <cuda_runtime.h>
#include <cuda_bf16.h>

#define NCAM 16

// FINAL — measured champion (R4, 43.07 us).
// Session findings baked in:
//  * ~1M threads / 2 points per thread is mandatory (fewer threads -> latency
//    collapse: R5 63us, R7 84us).
//  * f32x2 packed math + dup-pair smem params: best measured variant; all
//    param-path alternatives (column pairs, const bank/LDCU, full unroll)
//    measured neutral at +0.6..+1.7us.
//  * __stcs evict-first stores are load-bearing: default policy leaves 126MB
//    of dirty L2 that flushes into the next graph replay (R12: +6.9us).
//  * The 43us plateau is the memory system's effective streaming-write
//    ceiling (~5 TB/s) for the 256MB output, not an SM-side limit.

// ---------- f32x2 packed-math helpers (sm_103a) ----------
__device__ __forceinline__ unsigned long long pk2(float a, float b) {
    unsigned long long r;
    asm("mov.b64 %0, {%1, %2};" : "=l"(r) : "f"(a), "f"(b));
    return r;
}
__device__ __forceinline__ void upk2(unsigned long long v, float& a, float& b) {
    asm("mov.b64 {%0, %1}, %2;" : "=f"(a), "=f"(b) : "l"(v));
}
__device__ __forceinline__ unsigned long long fma2(unsigned long long a,
                                                   unsigned long long b,
                                                   unsigned long long c) {
    unsigned long long d;
    asm("fma.rn.f32x2 %0, %1, %2, %3;" : "=l"(d) : "l"(a), "l"(b), "l"(c));
    return d;
}
__device__ __forceinline__ unsigned long long mul2(unsigned long long a,
                                                   unsigned long long b) {
    unsigned long long d;
    asm("mul.rn.f32x2 %0, %1, %2;" : "=l"(d) : "l"(a), "l"(b));
    return d;
}
__device__ __forceinline__ float frcp(float x) {
    float r;
    asm("rcp.approx.f32 %0, %1;" : "=f"(r) : "f"(x));
    return r;
}

// Shared param layout per camera: 16 duplicated (v,v) pairs (128 B):
//   k 0..8 : r00 r01 r02 r10 r11 r12 r20 r21 r22
//   k 9..11: t0 t1 t2    k 12,13: f0 f1    k 14,15: c0 c1
// each stored as (v, v) so it is directly an f32x2 broadcast operand.

__global__ __launch_bounds__(256, 5)
void Projection_19713899889207_kernel(
    const float* __restrict__ pt3d,   // (3, Np) SoA
    const float* __restrict__ R,      // (NC, 3, 3)
    const float* __restrict__ t,      // (NC, 3)
    const float* __restrict__ f,      // (NC, 2)
    const float* __restrict__ c,      // (NC, 2)
    float* __restrict__ out,          // (NC*Np, 2)
    int np)
{
    __shared__ __align__(16) float sp[NCAM * 32];

    const int tid = threadIdx.x;
    // stage 512 floats with 256 threads (2 each)
    #pragma unroll
    for (int s = tid; s < NCAM * 32; s += 256) {
        const int cam = s >> 5;
        const int k   = (s & 31) >> 1;
        float v;
        if (k < 9)       v = R[cam * 9 + k];
        else if (k < 12) v = t[cam * 3 + (k - 9)];
        else if (k < 14) v = f[cam * 2 + (k - 12)];
        else             v = c[cam * 2 + (k - 14)];
        sp[s] = v;
    }
    __syncthreads();

    const int i = blockIdx.x * blockDim.x + tid;   // index of a PAIR of points
    const int np2 = np >> 1;
    if (i >= np2) return;

    // Two adjacent floats loaded as u64 == the f32x2 operand (x_j, x_{j+1}).
    const unsigned long long x01 =
        __ldg(reinterpret_cast<const unsigned long long*>(pt3d) + i);
    const unsigned long long y01 =
        __ldg(reinterpret_cast<const unsigned long long*>(pt3d + (size_t)np) + i);
    const unsigned long long z01 =
        __ldg(reinterpret_cast<const unsigned long long*>(pt3d + 2 * (size_t)np) + i);

    // Incremental output pointer: one float4 (2 points) per camera.
    float4* o = reinterpret_cast<float4*>(out) + (size_t)i;
    const size_t cam_stride_f4 = (size_t)(np >> 1);

    #pragma unroll 1
    for (int cam = 0; cam < NCAM; ++cam) {
        const ulonglong2* Q = reinterpret_cast<const ulonglong2*>(sp + cam * 32);
        const ulonglong2 q0 = Q[0];  // (r00d, r01d)
        const ulonglong2 q1 = Q[1];  // (r02d, r10d)
        const ulonglong2 q2 = Q[2];  // (r11d, r12d)
        const ulonglong2 q3 = Q[3];  // (r20d, r21d)
        const ulonglong2 q4 = Q[4];  // (r22d, t0d)
        const ulonglong2 q5 = Q[5];  // (t1d,  t2d)
        const ulonglong2 q6 = Q[6];  // (f0d,  f1d)
        const ulonglong2 q7 = Q[7];  // (c0d,  c1d)

        // Rotation + translation, two points per packed op.
        const unsigned long long X =
            fma2(q0.x, x01, fma2(q0.y, y01, fma2(q1.x, z01, q4.y)));
        const unsigned long long Y =
            fma2(q1.y, x01, fma2(q2.x, y01, fma2(q2.y, z01, q5.x)));
        const unsigned long long Z =
            fma2(q3.x, x01, fma2(q3.y, y01, fma2(q4.x, z01, q5.y)));

        float z0, z1;
        upk2(Z, z0, z1);
        const unsigned long long IZ = pk2(frcp(z0), frcp(z1));

        const unsigned long long U = fma2(mul2(X, IZ), q6.x, q7.x);
        const unsigned long long V = fma2(mul2(Y, IZ), q6.y, q7.y);

        float u0, u1, v0, v1;
        upk2(U, u0, u1);
        upk2(V, v0, v1);

        // streaming store (.cs evict-first is load-bearing — see header note)
        __stcs(o, make_float4(u0, v0, u1, v1));
        o += cam_stride_f4;
    }
}

extern "C" void kernel_launch(void* const* d_in, const int* in_sizes, int n_in,
                              void* d_out, int out_size)
{
    // metadata order: pt3d (3,Np) f32, R (16,3,3) f32, t (16,3) f32,
    //                 f (16,2) f32, c (16,2) f32, mask (16,Np) i32 (unused)
    const float* pt3d = (const float*)d_in[0];
    const float* R    = (const float*)d_in[1];
    const float* t    = (const float*)d_in[2];
    const float* f    = (const float*)d_in[3];
    const float* c    = (const float*)d_in[4];
    float* out        = (float*)d_out;

    const int np  = in_sizes[0] / 3;        // 2,000,000
    const int np2 = np / 2;
    const int threads = 256;
    const int blocks  = (np2 + threads - 1) / threads;

    Projection_19713899889207_kernel<<<blocks, threads>>>(pt3d, R, t, f, c, out, np);
}